// round 3
// baseline (speedup 1.0000x reference)
#include <cuda_runtime.h>
#include <cuda_bf16.h>

#define NMAX 100000
#define EMAX 1600000

// Scratch (device globals; no allocation allowed).
__device__ float4 g_h1[NMAX * 16];    // N x 64  (x@W1)   ; reused as decoder hidden (N x 64)
__device__ float4 g_acc1[NMAX * 16];  // N x 64  agg accum -> z1 after post1 (in place)
__device__ float4 g_h2[NMAX * 8];     // N x 32  (z1@W2)
__device__ float4 g_acc2[NMAX * 8];   // N x 32  agg accum -> z after post2 (in place)
__device__ float4 g_deg4[NMAX / 4];   // degree (viewed as float[NMAX])
__device__ float  g_dinv[NMAX];
__device__ int    g_src[EMAX];
__device__ int    g_dst[EMAX];
__device__ float  g_norm[EMAX];
__device__ int    g_is64;             // 1 if edge_index is int64, 0 if int32

// ---------------------------------------------------------------------------
// Detect edge_index dtype: for int64 (little-endian), every odd 32-bit word is
// the high half of a small non-negative value -> 0. For int32, odd words are
// random node ids (~0.001% chance of being 0 each).
__global__ void detect_kernel(const int* __restrict__ ei_raw) {
    if (threadIdx.x == 0) {
        int all_zero = 1;
        for (int k = 1; k < 256; k += 2)
            if (ei_raw[k] != 0) { all_zero = 0; break; }
        g_is64 = all_zero;
    }
}

// Convert indices -> int32 (clamped for safety).
__global__ void prep_idx_kernel(const void* __restrict__ ei_raw, int e, int n) {
    int i = blockIdx.x * blockDim.x + threadIdx.x;
    if (i >= e) return;
    int s, d;
    if (g_is64) {
        const long long* p = (const long long*)ei_raw;
        s = (int)p[i];
        d = (int)p[e + i];
    } else {
        const int* p = (const int*)ei_raw;
        s = p[i];
        d = p[e + i];
    }
    s = min(max(s, 0), n - 1);
    d = min(max(d, 0), n - 1);
    g_src[i] = s;
    g_dst[i] = d;
}

// Zero accumulators + degree in one kernel.
__global__ void zero_kernel(int n) {
    int i = blockIdx.x * blockDim.x + threadIdx.x;
    int t1 = n * 16;            // acc1 float4s
    int t2 = t1 + n * 8;        // acc2 float4s
    int t3 = t2 + (n >> 2);     // deg float4s
    float4 z = make_float4(0.f, 0.f, 0.f, 0.f);
    if (i < t1)       g_acc1[i] = z;
    else if (i < t2)  g_acc2[i - t1] = z;
    else if (i < t3)  g_deg4[i - t2] = z;
}

// Degree: count edges by destination (from converted int32 indices).
__global__ void deg_kernel(int e) {
    int i = blockIdx.x * blockDim.x + threadIdx.x;
    if (i >= e) return;
    float* deg = reinterpret_cast<float*>(g_deg4);
    atomicAdd(&deg[g_dst[i]], 1.0f);
}

// dinv = rsqrt(deg + 1)   (+1 = self loop; always > 0)
__global__ void dinv_kernel(int n) {
    int i = blockIdx.x * blockDim.x + threadIdx.x;
    if (i >= n) return;
    const float* deg = reinterpret_cast<const float*>(g_deg4);
    g_dinv[i] = rsqrtf(deg[i] + 1.0f);
}

// Precompute per-edge norm.
__global__ void norm_kernel(int e) {
    int i = blockIdx.x * blockDim.x + threadIdx.x;
    if (i >= e) return;
    g_norm[i] = g_dinv[g_src[i]] * g_dinv[g_dst[i]];
}

// ---------------------------------------------------------------------------
// Edge aggregation: thread = (edge, float4-chunk). float4 atomics (sm_90+).
template <int C4>
__global__ void agg_kernel(const float4* __restrict__ h, float4* __restrict__ acc, int e) {
    int idx = blockIdx.x * blockDim.x + threadIdx.x;
    int ed = idx / C4;
    if (ed >= e) return;
    int c = idx - ed * C4;
    int s = g_src[ed];
    int d = g_dst[ed];
    float nrm = g_norm[ed];
    float4 v = h[(long long)s * C4 + c];
    v.x *= nrm; v.y *= nrm; v.z *= nrm; v.w *= nrm;
    atomicAdd(&acc[(long long)d * C4 + c], v);
}

// Epilogue: add self-loop term (h[i]*dinv[i]^2) + bias, optional ReLU,
// in-place into acc, optional copy to out2.
template <int C4, bool RELU>
__global__ void post_kernel(float4* __restrict__ acc, const float4* __restrict__ h,
                            const float4* __restrict__ bias, float4* __restrict__ out2, int n) {
    int idx = blockIdx.x * blockDim.x + threadIdx.x;
    if (idx >= n * C4) return;
    int i = idx / C4;
    int c = idx - i * C4;
    float di = g_dinv[i];
    float sl = di * di;
    float4 a = acc[idx];
    float4 hv = h[idx];
    float4 b = bias[c];
    a.x += hv.x * sl + b.x;
    a.y += hv.y * sl + b.y;
    a.z += hv.z * sl + b.z;
    a.w += hv.w * sl + b.w;
    if (RELU) {
        a.x = fmaxf(a.x, 0.f); a.y = fmaxf(a.y, 0.f);
        a.z = fmaxf(a.z, 0.f); a.w = fmaxf(a.w, 0.f);
    }
    acc[idx] = a;
    if (out2) out2[idx] = a;
}

// ---------------------------------------------------------------------------
// Small dense GEMM: out[n,KO] = in[n,KI] @ W[KI,KO] (+bias, +relu).
// W staged in smem; block handles RPB rows; thread computes a float4 of outputs.
template <int KI, int KO, bool BIAS, bool RELU>
__global__ void gemm_kernel(const float* __restrict__ in, const float* __restrict__ W,
                            const float* __restrict__ bias, float* __restrict__ out, int n) {
    constexpr int TPR = KO / 4;     // threads per row
    constexpr int RPB = 256 / TPR;  // rows per block
    __shared__ float ws[KI * KO];
    __shared__ float xs[RPB * KI];

    int tid = threadIdx.x;
    for (int i = tid; i < KI * KO / 4; i += 256)
        reinterpret_cast<float4*>(ws)[i] = reinterpret_cast<const float4*>(W)[i];

    int row0 = blockIdx.x * RPB;
    const float4* inr = reinterpret_cast<const float4*>(in + (long long)row0 * KI);
    for (int i = tid; i < RPB * KI / 4; i += 256)
        reinterpret_cast<float4*>(xs)[i] = inr[i];
    __syncthreads();

    int r = tid / TPR;
    int c = (tid - r * TPR) * 4;
    float4 acc = make_float4(0.f, 0.f, 0.f, 0.f);
    const float* xr = xs + r * KI;
#pragma unroll
    for (int k = 0; k < KI; k++) {
        float xv = xr[k];
        float4 w = *reinterpret_cast<const float4*>(&ws[k * KO + c]);
        acc.x += xv * w.x; acc.y += xv * w.y;
        acc.z += xv * w.z; acc.w += xv * w.w;
    }
    if (BIAS) {
        float4 b = *reinterpret_cast<const float4*>(&bias[c]);
        acc.x += b.x; acc.y += b.y; acc.z += b.z; acc.w += b.w;
    }
    if (RELU) {
        acc.x = fmaxf(acc.x, 0.f); acc.y = fmaxf(acc.y, 0.f);
        acc.z = fmaxf(acc.z, 0.f); acc.w = fmaxf(acc.w, 0.f);
    }
    *reinterpret_cast<float4*>(&out[(long long)(row0 + r) * KO + c]) = acc;
}

// ---------------------------------------------------------------------------
extern "C" void kernel_launch(void* const* d_in, const int* in_sizes, int n_in,
                              void* d_out, int out_size) {
    const float* x       = (const float*)d_in[0];
    const void*  ei      = d_in[1];
    const float* W1      = (const float*)d_in[2];
    const float* b1      = (const float*)d_in[3];
    const float* W2      = (const float*)d_in[4];
    const float* b2      = (const float*)d_in[5];
    const float* Wd1     = (const float*)d_in[6];
    const float* bd1     = (const float*)d_in[7];
    const float* Wd2     = (const float*)d_in[8];
    const float* bd2     = (const float*)d_in[9];

    int n = in_sizes[0] / 128;   // 100000
    int e = in_sizes[1] / 2;     // 1600000

    float* rec_out = (float*)d_out;                       // [N,128]
    float* z_out   = rec_out + (long long)n * 128;        // [N,32]

    // Resolve scratch addresses (host-side symbol lookups; no allocation).
    void *p_h1, *p_acc1, *p_h2, *p_acc2;
    cudaGetSymbolAddress(&p_h1,   g_h1);
    cudaGetSymbolAddress(&p_acc1, g_acc1);
    cudaGetSymbolAddress(&p_h2,   g_h2);
    cudaGetSymbolAddress(&p_acc2, g_acc2);
    float4* h1   = (float4*)p_h1;
    float4* acc1 = (float4*)p_acc1;
    float4* h2   = (float4*)p_h2;
    float4* acc2 = (float4*)p_acc2;

    const int B = 256;
    int zero_total = n * 24 + (n >> 2);

    detect_kernel<<<1, 32>>>((const int*)ei);
    prep_idx_kernel<<<(e + B - 1) / B, B>>>(ei, e, n);
    zero_kernel<<<(zero_total + B - 1) / B, B>>>(n);
    deg_kernel<<<(e + B - 1) / B, B>>>(e);
    dinv_kernel<<<(n + B - 1) / B, B>>>(n);
    norm_kernel<<<(e + B - 1) / B, B>>>(e);

    // Layer 1: h1 = x @ W1 ; aggregate ; z1 = relu(agg + self + b1)  (in acc1)
    gemm_kernel<128, 64, false, false><<<n / 16, B>>>(x, W1, nullptr, (float*)h1, n);
    agg_kernel<16><<<(e * 16 + B - 1) / B, B>>>(h1, acc1, e);
    post_kernel<16, true><<<(n * 16 + B - 1) / B, B>>>(acc1, h1, (const float4*)b1, nullptr, n);

    // Layer 2: h2 = z1 @ W2 ; aggregate ; z = agg + self + b2  (in acc2, copied to z_out)
    gemm_kernel<64, 32, false, false><<<n / 32, B>>>((const float*)acc1, W2, nullptr, (float*)h2, n);
    agg_kernel<8><<<(e * 8 + B - 1) / B, B>>>(h2, acc2, e);
    post_kernel<8, false><<<(n * 8 + B - 1) / B, B>>>(acc2, h2, (const float4*)b2, (float4*)z_out, n);

    // Decoder: h = relu(z @ Wd1 + bd1) ; rec = h @ Wd2 + bd2
    gemm_kernel<32, 64, true, true><<<n / 16, B>>>((const float*)acc2, Wd1, bd1, (float*)h1, n);
    gemm_kernel<64, 128, true, false><<<n / 8, B>>>((const float*)h1, Wd2, bd2, rec_out, n);
}